// round 1
// baseline (speedup 1.0000x reference)
#include <cuda_runtime.h>
#include <cstdint>
#include <cstddef>

// NeuralCTLSTM fused kernel:
//   gates[g,b,o] = sum_h h_ti[b,h] * W[g,o,h] + bias[g,o]   (tf32 tensor-core GEMM)
//   + fused CT-LSTM epilogue producing (o_g, h_new, c_new, cbar_new, decay_t).
//
// B=65536, H=256, G=7. CTA tile: 128 (b) x 32 (o) x 7 gates, K chunks of 32,
// cp.async double-buffered. 512 threads = 16 warps (4m x 4o), warp tile m32 x o8
// per gate via mma.sync.m16n8k8.tf32 (fp32 accumulate).

#define BD   512
#define BM   128
#define BO   32
#define BK   32
#define NG   7
#define HH   256
#define SSTR 36                  // padded smem row stride (floats)
#define HS_FLOATS (BM * SSTR)            // 4608
#define WS_FLOATS (NG * BO * SSTR)       // 8064
#define STAGE_FLOATS (HS_FLOATS + WS_FLOATS) // 12672

__device__ __forceinline__ uint32_t f2tf32(float f) {
    uint32_t u;
    asm("cvt.rna.tf32.f32 %0, %1;" : "=r"(u) : "f"(f));
    return u;
}

__device__ __forceinline__ void mma_tf32(float* d, const uint32_t* a, const uint32_t* b) {
    asm volatile(
        "mma.sync.aligned.m16n8k8.row.col.f32.tf32.tf32.f32 "
        "{%0,%1,%2,%3}, {%4,%5,%6,%7}, {%8,%9}, {%0,%1,%2,%3};\n"
        : "+f"(d[0]), "+f"(d[1]), "+f"(d[2]), "+f"(d[3])
        : "r"(a[0]), "r"(a[1]), "r"(a[2]), "r"(a[3]),
          "r"(b[0]), "r"(b[1]));
}

__device__ __forceinline__ void cp_async16(uint32_t dst_smem, const void* src) {
    asm volatile("cp.async.cg.shared.global [%0], [%1], 16;\n"
                 :: "r"(dst_smem), "l"(src));
}

__device__ __forceinline__ void load_chunk(
    uint32_t sbase, const float* __restrict__ h_ti, const float* __restrict__ W,
    int b0, int o0, int kc, int tid)
{
    // h tile: 128 rows x 32 cols -> 1024 float4 loads
#pragma unroll
    for (int i = 0; i < 2; i++) {
        int idx = tid + i * BD;          // 0..1023
        int row = idx >> 3;
        int c4  = idx & 7;
        cp_async16(sbase + (uint32_t)(row * SSTR + c4 * 4) * 4u,
                   h_ti + (size_t)(b0 + row) * HH + kc + c4 * 4);
    }
    // W tile: 7 gates x 32 rows x 32 cols -> 1792 float4 loads
    uint32_t wbase = sbase + (uint32_t)HS_FLOATS * 4u;
#pragma unroll
    for (int i = 0; i < 4; i++) {
        int idx = tid + i * BD;
        if (idx < NG * BO * 8) {         // 1792
            int g   = idx >> 8;          // /256
            int rem = idx & 255;
            int row = rem >> 3;
            int c4  = rem & 7;
            cp_async16(wbase + (uint32_t)((g * BO + row) * SSTR + c4 * 4) * 4u,
                       W + ((size_t)(g * HH + o0 + row)) * HH + kc + c4 * 4);
        }
    }
    asm volatile("cp.async.commit_group;\n");
}

__device__ __forceinline__ float sigmoidf_fast(float x) {
    return 1.0f / (1.0f + __expf(-x));
}

extern "C" __global__ void __launch_bounds__(BD, 1)
nctlstm_fused_kernel(const float* __restrict__ inter_times,
                     const float* __restrict__ h_ti,
                     const float* __restrict__ c_ti,
                     const float* __restrict__ cbar,
                     const float* __restrict__ W,
                     const float* __restrict__ bias,
                     float* __restrict__ out,
                     int Btot)
{
    extern __shared__ float smem[];

    const int tid  = threadIdx.x;
    const int lane = tid & 31;
    const int warp = tid >> 5;
    const int wr   = warp >> 2;   // 0..3 : m-warp
    const int wc   = warp & 3;    // 0..3 : o-warp
    const int grp  = lane >> 2;   // 0..7
    const int tig  = lane & 3;    // 0..3

    const int b0 = blockIdx.y * BM;
    const int o0 = blockIdx.x * BO;

    // accumulators: [gate][m-tile][c0..c3], init with bias (bias[g,o])
    const int ocol = o0 + wc * 8 + 2 * tig;   // even column, float2-aligned
    float acc[NG][2][4];
#pragma unroll
    for (int g = 0; g < NG; g++) {
        float2 bv = *reinterpret_cast<const float2*>(bias + (size_t)g * HH + ocol);
#pragma unroll
        for (int mt = 0; mt < 2; mt++) {
            acc[g][mt][0] = bv.x; acc[g][mt][1] = bv.y;
            acc[g][mt][2] = bv.x; acc[g][mt][3] = bv.y;
        }
    }

    const uint32_t smem_base = (uint32_t)__cvta_generic_to_shared(smem);

    // prologue: prefetch chunk 0
    load_chunk(smem_base, h_ti, W, b0, o0, 0, tid);

    const int NCHUNK = HH / BK;   // 8
    for (int c = 0; c < NCHUNK; c++) {
        const int stage = c & 1;
        if (c + 1 < NCHUNK) {
            load_chunk(smem_base + (uint32_t)(((c + 1) & 1) * STAGE_FLOATS) * 4u,
                       h_ti, W, b0, o0, (c + 1) * BK, tid);
            asm volatile("cp.async.wait_group 1;\n");
        } else {
            asm volatile("cp.async.wait_group 0;\n");
        }
        __syncthreads();

        const float* hs = smem + stage * STAGE_FLOATS;
        const float* ws = hs + HS_FLOATS;

#pragma unroll
        for (int ks = 0; ks < 4; ks++) {
            const int k0 = ks * 8;
            uint32_t a[2][4];
#pragma unroll
            for (int mt = 0; mt < 2; mt++) {
                const int r = wr * 32 + mt * 16 + grp;
                a[mt][0] = f2tf32(hs[r * SSTR + k0 + tig]);
                a[mt][1] = f2tf32(hs[(r + 8) * SSTR + k0 + tig]);
                a[mt][2] = f2tf32(hs[r * SSTR + k0 + tig + 4]);
                a[mt][3] = f2tf32(hs[(r + 8) * SSTR + k0 + tig + 4]);
            }
            const int orow = wc * 8 + grp;
#pragma unroll
            for (int g = 0; g < NG; g++) {
                uint32_t bf[2];
                bf[0] = f2tf32(ws[(g * BO + orow) * SSTR + k0 + tig]);
                bf[1] = f2tf32(ws[(g * BO + orow) * SSTR + k0 + tig + 4]);
                mma_tf32(acc[g][0], a[0], bf);
                mma_tf32(acc[g][1], a[1], bf);
            }
        }
        __syncthreads();
    }

    // ---- fused epilogue (all 7 gates for each (b,o) live in this thread) ----
    const size_t BHtot = (size_t)Btot * HH;

#pragma unroll
    for (int mt = 0; mt < 2; mt++) {
#pragma unroll
        for (int rs = 0; rs < 2; rs++) {
            const int b  = b0 + wr * 32 + mt * 16 + grp + rs * 8;
            const float dt = inter_times[b];
            const size_t base = (size_t)b * HH + ocol;
            const float2 cv = *reinterpret_cast<const float2*>(c_ti + base);
            const float2 cb = *reinterpret_cast<const float2*>(cbar + base);

            float2 r_og, r_hn, r_cn, r_cbn, r_dec;
#pragma unroll
            for (int j = 0; j < 2; j++) {
                const int ai = rs * 2 + j;
                const float gi  = acc[0][mt][ai];
                const float gf  = acc[1][mt][ai];
                const float goo = acc[2][mt][ai];
                const float gib = acc[3][mt][ai];
                const float gfb = acc[4][mt][ai];
                const float gz  = acc[5][mt][ai];
                const float gd  = acc[6][mt][ai];

                const float i_g   = sigmoidf_fast(gi);
                const float f_g   = sigmoidf_fast(gf);
                const float o_g   = sigmoidf_fast(goo);
                const float ib_g  = sigmoidf_fast(gib);
                const float fb_g  = sigmoidf_fast(gfb);
                const float z     = tanhf(gz);
                // stable softplus: max(x,0) + log1p(exp(-|x|))
                const float decay = fmaxf(gd, 0.0f) + log1pf(__expf(-fabsf(gd)));

                const float ct  = (j == 0) ? cv.x : cv.y;
                const float cbv = (j == 0) ? cb.x : cb.y;

                const float e       = __expf(-decay * dt);
                const float c_after = cbv + (ct - cbv) * e;
                const float c_new   = f_g * c_after + i_g * z;
                const float cb_new  = fb_g * cbv + ib_g * z;
                const float h_new   = o_g * tanhf(c_after);

                if (j == 0) { r_og.x = o_g; r_hn.x = h_new; r_cn.x = c_new; r_cbn.x = cb_new; r_dec.x = decay; }
                else        { r_og.y = o_g; r_hn.y = h_new; r_cn.y = c_new; r_cbn.y = cb_new; r_dec.y = decay; }
            }
            *reinterpret_cast<float2*>(out + 0 * BHtot + base) = r_og;
            *reinterpret_cast<float2*>(out + 1 * BHtot + base) = r_hn;
            *reinterpret_cast<float2*>(out + 2 * BHtot + base) = r_cn;
            *reinterpret_cast<float2*>(out + 3 * BHtot + base) = r_cbn;
            *reinterpret_cast<float2*>(out + 4 * BHtot + base) = r_dec;
        }
    }
}

extern "C" void kernel_launch(void* const* d_in, const int* in_sizes, int n_in,
                              void* d_out, int out_size)
{
    const float* inter_times = (const float*)d_in[0];   // (B,)
    const float* h_ti        = (const float*)d_in[1];   // (B,H)
    const float* c_ti        = (const float*)d_in[2];   // (B,H)
    const float* cbar        = (const float*)d_in[3];   // (B,H)
    const float* W           = (const float*)d_in[4];   // (G,H,H)
    const float* bias        = (const float*)d_in[5];   // (G,H)

    const int B = in_sizes[0];

    const size_t smem_bytes = 2 * (size_t)STAGE_FLOATS * sizeof(float); // 101376
    cudaFuncSetAttribute(nctlstm_fused_kernel,
                         cudaFuncAttributeMaxDynamicSharedMemorySize,
                         (int)smem_bytes);

    dim3 grid(HH / BO, B / BM);   // (8, 512) — o fastest for L2 h-tile reuse
    nctlstm_fused_kernel<<<grid, BD, smem_bytes>>>(
        inter_times, h_ti, c_ti, cbar, W, bias, (float*)d_out, B);
}

// round 3
// speedup vs baseline: 1.2261x; 1.2261x over previous
#include <cuda_runtime.h>
#include <cstdint>
#include <cstddef>

// Legacy-path (mma.sync m16n8k8.tf32) fused NeuralCTLSTM.
//   gates[g,b,o] = sum_h h[b,h]*W[g,o,h] + bias[g,o]  -> CT-LSTM epilogue.
// W block (7g x 16o x 256k = 112KB) resident in smem, pre-permuted into
// fragment order (LDS.128 per B-frag pair). A double-buffered via cp.async.
// Persistent: grid (16 o-blocks x 37), each CTA loops b-tiles of 256 rows.

#define NG 7
#define HH 256
#define BM 256
#define BO 16
#define BK 32
#define NCHUNK 8
#define GY 37
#define THREADS 512

#define SSTR 36                              // padded A row stride (floats)
#define W_BYTES (NG * BO * HH * 4)           // 114688
#define A_STAGE_BYTES (BM * SSTR * 4)        // 36864
#define OFF_A W_BYTES
#define SMEM_BYTES (W_BYTES + 2 * A_STAGE_BYTES)   // 188416

__device__ __forceinline__ uint32_t f2tf32(float f) {
    uint32_t u;
    asm("cvt.rna.tf32.f32 %0, %1;" : "=r"(u) : "f"(f));
    return u;
}

__device__ __forceinline__ void mma_tf32(float* d, const uint32_t* a, const uint32_t* b) {
    asm volatile(
        "mma.sync.aligned.m16n8k8.row.col.f32.tf32.tf32.f32 "
        "{%0,%1,%2,%3}, {%4,%5,%6,%7}, {%8,%9}, {%0,%1,%2,%3};\n"
        : "+f"(d[0]), "+f"(d[1]), "+f"(d[2]), "+f"(d[3])
        : "r"(a[0]), "r"(a[1]), "r"(a[2]), "r"(a[3]),
          "r"(b[0]), "r"(b[1]));
}

__device__ __forceinline__ void cp_async16(uint32_t dst, const void* src) {
    asm volatile("cp.async.cg.shared.global [%0], [%1], 16;\n" :: "r"(dst), "l"(src));
}

__device__ __forceinline__ float tanh_fast(float x) {
    float y;
    asm("tanh.approx.f32 %0, %1;" : "=f"(y) : "f"(x));
    return y;
}
__device__ __forceinline__ float sigm(float x) {       // 0.5*tanh(x/2)+0.5
    return fmaf(tanh_fast(0.5f * x), 0.5f, 0.5f);
}

extern "C" __global__ void __launch_bounds__(THREADS, 1)
nctlstm_wres_kernel(const float* __restrict__ inter_times,
                    const float* __restrict__ h_ti,
                    const float* __restrict__ c_ti,
                    const float* __restrict__ cbar,
                    const float* __restrict__ W,
                    const float* __restrict__ bias,
                    float* __restrict__ out,
                    int Btot)
{
    extern __shared__ char smem[];
    const uint32_t sb = (uint32_t)__cvta_generic_to_shared(smem);
    uint4* wperm = reinterpret_cast<uint4*>(smem);

    const int tid  = threadIdx.x;
    const int warp = tid >> 5;
    const int lane = tid & 31;
    const int grp  = lane >> 2;      // 0..7
    const int tig  = lane & 3;       // 0..3
    const int wr   = warp >> 1;      // 0..7 : m-warp
    const int wc   = warp & 1;       // 0..1 : o-warp

    const int o0  = blockIdx.x * BO;
    const int by  = blockIdx.y;
    const int nbt = Btot / BM;       // 256

    // ---- A stage loader: 2048 x 16B granules, 4 per thread ----
    auto load_A = [&](int tile, int ch, int s) {
        const uint32_t ab = sb + OFF_A + (uint32_t)s * A_STAGE_BYTES;
        const float* src = h_ti + (size_t)tile * BM * HH + ch * BK;
#pragma unroll
        for (int i = 0; i < 4; i++) {
            int idx = tid + i * THREADS;
            int r = idx >> 3, c4 = idx & 7;
            cp_async16(ab + (uint32_t)(r * (SSTR * 4) + c4 * 16),
                       src + (size_t)r * HH + c4 * 4);
        }
        asm volatile("cp.async.commit_group;\n");
    };

    // prologue: first tile chunk0 in flight during W permute
    int t0 = by;
    load_A(t0, 0, 0);

    // ---- one-time W permute into fragment order (rna-rounded tf32) ----
    // unit u -> (p=u&1, ch=(u>>1)&7, wcc=(u>>4)&1, g=u>>5); 224 units.
    for (int u = warp; u < NG * 2 * NCHUNK * 2; u += 16) {
        const int p = u & 1, ch = (u >> 1) & 7, wcc = (u >> 4) & 1, g = u >> 5;
        const int o = o0 + wcc * 8 + grp;
        const int k = ch * 32 + p * 16 + tig;
        const float* wsrc = W + ((size_t)g * HH + o) * HH + k;
        uint4 v;
        v.x = f2tf32(wsrc[0]);
        v.y = f2tf32(wsrc[4]);
        v.z = f2tf32(wsrc[8]);
        v.w = f2tf32(wsrc[12]);
        wperm[u * 32 + lane] = v;
    }

    // bias held in registers (acc init value)
    const int ocol = o0 + wc * 8 + 2 * tig;
    float2 bv[NG];
#pragma unroll
    for (int g = 0; g < NG; g++)
        bv[g] = *reinterpret_cast<const float2*>(bias + (size_t)g * HH + ocol);

    const size_t BHtot = (size_t)Btot * HH;

    for (int t = t0; t < nbt; t += GY) {
        float acc[NG][2][4];
#pragma unroll
        for (int g = 0; g < NG; g++)
#pragma unroll
            for (int mt = 0; mt < 2; mt++) {
                acc[g][mt][0] = bv[g].x; acc[g][mt][1] = bv[g].y;
                acc[g][mt][2] = bv[g].x; acc[g][mt][3] = bv[g].y;
            }

#pragma unroll 1
        for (int ch = 0; ch < NCHUNK; ch++) {
            // issue next A load (next chunk, or next tile's chunk0)
            bool pending = true;
            if (ch + 1 < NCHUNK)       load_A(t, ch + 1, (ch + 1) & 1);
            else if (t + GY < nbt)     load_A(t + GY, 0, 0);
            else                       pending = false;
            if (pending) asm volatile("cp.async.wait_group 1;\n");
            else         asm volatile("cp.async.wait_group 0;\n");
            __syncthreads();

            const float* hs = reinterpret_cast<const float*>(
                smem + OFF_A + (ch & 1) * A_STAGE_BYTES);

#pragma unroll
            for (int p = 0; p < 2; p++) {
                uint32_t a[2][2][4];      // [ks-in-pair][mt][frag]
#pragma unroll
                for (int q = 0; q < 2; q++) {
                    const int k0 = (2 * p + q) * 8;
#pragma unroll
                    for (int mt = 0; mt < 2; mt++) {
                        const int r = wr * 32 + mt * 16 + grp;
                        a[q][mt][0] = __float_as_uint(hs[r * SSTR + k0 + tig]);
                        a[q][mt][1] = __float_as_uint(hs[(r + 8) * SSTR + k0 + tig]);
                        a[q][mt][2] = __float_as_uint(hs[r * SSTR + k0 + tig + 4]);
                        a[q][mt][3] = __float_as_uint(hs[(r + 8) * SSTR + k0 + tig + 4]);
                    }
                }
#pragma unroll
                for (int g = 0; g < NG; g++) {
                    const uint4 wf = wperm[(((g * 2 + wc) * 8 + ch) * 2 + p) * 32 + lane];
                    uint32_t b0[2] = {wf.x, wf.y};
                    uint32_t b1[2] = {wf.z, wf.w};
                    mma_tf32(acc[g][0], a[0][0], b0);
                    mma_tf32(acc[g][1], a[0][1], b0);
                    mma_tf32(acc[g][0], a[1][0], b1);
                    mma_tf32(acc[g][1], a[1][1], b1);
                }
            }
            __syncthreads();
        }

        // ---- fused epilogue (bias already in acc) ----
#pragma unroll
        for (int mt = 0; mt < 2; mt++) {
#pragma unroll
            for (int rs = 0; rs < 2; rs++) {
                const int b = t * BM + wr * 32 + mt * 16 + grp + rs * 8;
                const float dt = inter_times[b];
                const size_t base = (size_t)b * HH + ocol;
                const float2 cv = *reinterpret_cast<const float2*>(c_ti + base);
                const float2 cb = *reinterpret_cast<const float2*>(cbar + base);

                float2 r_o, r_h, r_c, r_cb, r_d;
#pragma unroll
                for (int j = 0; j < 2; j++) {
                    const int ai = rs * 2 + j;
                    const float gi  = acc[0][mt][ai];
                    const float gf  = acc[1][mt][ai];
                    const float go  = acc[2][mt][ai];
                    const float gib = acc[3][mt][ai];
                    const float gfb = acc[4][mt][ai];
                    const float gz  = acc[5][mt][ai];
                    const float gd  = acc[6][mt][ai];

                    const float i_g  = sigm(gi);
                    const float f_g  = sigm(gf);
                    const float o_g  = sigm(go);
                    const float ib_g = sigm(gib);
                    const float fb_g = sigm(gfb);
                    const float z    = tanh_fast(gz);
                    const float decay = fmaxf(gd, 0.0f)
                                      + __logf(1.0f + __expf(-fabsf(gd)));

                    const float ct  = (j == 0) ? cv.x : cv.y;
                    const float cbv = (j == 0) ? cb.x : cb.y;

                    const float e       = __expf(-decay * dt);
                    const float c_after = cbv + (ct - cbv) * e;
                    const float c_new   = f_g * c_after + i_g * z;
                    const float cb_new  = fb_g * cbv + ib_g * z;
                    const float h_new   = o_g * tanh_fast(c_after);

                    if (j == 0) { r_o.x = o_g; r_h.x = h_new; r_c.x = c_new; r_cb.x = cb_new; r_d.x = decay; }
                    else        { r_o.y = o_g; r_h.y = h_new; r_c.y = c_new; r_cb.y = cb_new; r_d.y = decay; }
                }
                *reinterpret_cast<float2*>(out + 0 * BHtot + base) = r_o;
                *reinterpret_cast<float2*>(out + 1 * BHtot + base) = r_h;
                *reinterpret_cast<float2*>(out + 2 * BHtot + base) = r_c;
                *reinterpret_cast<float2*>(out + 3 * BHtot + base) = r_cb;
                *reinterpret_cast<float2*>(out + 4 * BHtot + base) = r_d;
            }
        }
    }
}

extern "C" void kernel_launch(void* const* d_in, const int* in_sizes, int n_in,
                              void* d_out, int out_size)
{
    const float* inter_times = (const float*)d_in[0];
    const float* h_ti        = (const float*)d_in[1];
    const float* c_ti        = (const float*)d_in[2];
    const float* cbar        = (const float*)d_in[3];
    const float* W           = (const float*)d_in[4];
    const float* bias        = (const float*)d_in[5];
    const int B = in_sizes[0];

    cudaFuncSetAttribute(nctlstm_wres_kernel,
                         cudaFuncAttributeMaxDynamicSharedMemorySize, SMEM_BYTES);

    dim3 grid(HH / BO, GY);   // (16, 37) = 592 CTAs = 4 exact waves @ 148 SMs
    nctlstm_wres_kernel<<<grid, THREADS, SMEM_BYTES>>>(
        inter_times, h_ti, c_ti, cbar, W, bias, (float*)d_out, B);
}